// round 5
// baseline (speedup 1.0000x reference)
#include <cuda_runtime.h>

#define NROWS 2048
#define DFEAT 128
#define BLOCK 256
#define NWARP (BLOCK / 32)

__global__ __launch_bounds__(BLOCK, 8) void distance_sparse_kernel(
    const float* __restrict__ feats,
    const float* __restrict__ adj,
    float* __restrict__ out)
{
    const int i    = blockIdx.x;
    const int tid  = threadIdx.x;
    const int lane = tid & 31;
    const int warp = tid >> 5;

    __shared__ unsigned short nzidx[NROWS];  // 4 KB
    __shared__ float          evals[NROWS];  // 8 KB
    __shared__ float          wpart[NWARP];
    __shared__ int            cnt;

    // ---- issue adj-row DRAM loads first (long pole) ----
    const float4* arow4 = reinterpret_cast<const float4*>(adj + (size_t)i * NROWS);
    const float4 a0 = arow4[tid];
    const float4 a1 = arow4[tid + BLOCK];

    // fi: lane l holds feats[i][4l..4l+3]
    const float4 fi = reinterpret_cast<const float4*>(feats + (size_t)i * DFEAT)[lane];

    if (tid == 0) cnt = 0;
    __syncthreads();

    // ---- Phase 1: ballot-compact nonzero columns ----
    const unsigned lt = (1u << lane) - 1u;
    #pragma unroll
    for (int c = 0; c < 2; c++) {
        const float4 av = (c == 0) ? a0 : a1;
        const int t = tid + c * BLOCK;
        const unsigned b0 = __ballot_sync(0xffffffffu, av.x != 0.0f);
        const unsigned b1 = __ballot_sync(0xffffffffu, av.y != 0.0f);
        const unsigned b2 = __ballot_sync(0xffffffffu, av.z != 0.0f);
        const unsigned b3 = __ballot_sync(0xffffffffu, av.w != 0.0f);
        const int c0 = __popc(b0), c1 = __popc(b1), c2 = __popc(b2), c3 = __popc(b3);
        int base = 0;
        if (lane == 0) base = atomicAdd(&cnt, c0 + c1 + c2 + c3);
        base = __shfl_sync(0xffffffffu, base, 0);
        const int col = t * 4;
        if (av.x != 0.0f) nzidx[base + __popc(b0 & lt)]                = (unsigned short)(col);
        if (av.y != 0.0f) nzidx[base + c0 + __popc(b1 & lt)]           = (unsigned short)(col + 1);
        if (av.z != 0.0f) nzidx[base + c0 + c1 + __popc(b2 & lt)]      = (unsigned short)(col + 2);
        if (av.w != 0.0f) nzidx[base + c0 + c1 + c2 + __popc(b3 & lt)] = (unsigned short)(col + 3);
    }
    __syncthreads();
    const int m = cnt;

    // ---- zero-fill output row (fire-and-forget; ordered before the scatter by
    //      the __syncthreads after the epilogue reduction) ----
    float4* orow4 = reinterpret_cast<float4*>(out + (size_t)i * NROWS);
    const float4 z = make_float4(0.f, 0.f, 0.f, 0.f);
    orow4[tid]         = z;
    orow4[tid + BLOCK] = z;

    // ---- Phase 2: one full warp per column, 2x unrolled, interleaved reductions ----
    for (int k = warp; k < m; k += 2 * NWARP) {
        const int  kB   = k + NWARP;
        const bool actB = kB < m;
        const int  jA   = (int)nzidx[k];
        const int  jB   = actB ? (int)nzidx[kB] : jA;
        const float4 fa = reinterpret_cast<const float4*>(feats + (size_t)jA * DFEAT)[lane];
        const float4 fb = reinterpret_cast<const float4*>(feats + (size_t)jB * DFEAT)[lane];

        float sA = (fabsf(fi.x - fa.x) + fabsf(fi.y - fa.y))
                 + (fabsf(fi.z - fa.z) + fabsf(fi.w - fa.w));
        float sB = (fabsf(fi.x - fb.x) + fabsf(fi.y - fb.y))
                 + (fabsf(fi.z - fb.z) + fabsf(fi.w - fb.w));
        #pragma unroll
        for (int o = 16; o >= 1; o >>= 1) {   // two independent 5-deep chains, pipelined
            sA += __shfl_xor_sync(0xffffffffu, sA, o);
            sB += __shfl_xor_sync(0xffffffffu, sB, o);
        }
        if (lane == 0) {
            evals[k] = sA;
            if (actB) evals[kB] = sB;
        }
    }
    __syncthreads();

    // ---- Phase 3a: batched exp + block reduction of rowsum ----
    float local = 0.0f;
    for (int t = tid; t < m; t += BLOCK) {
        const float e = __expf(-0.01f * evals[t]);
        evals[t] = e;
        local += e;
    }
    #pragma unroll
    for (int o = 16; o >= 1; o >>= 1)
        local += __shfl_xor_sync(0xffffffffu, local, o);
    if (lane == 0) wpart[warp] = local;
    __syncthreads();
    if (tid == 0) {
        float s = 0.0f;
        #pragma unroll
        for (int w = 0; w < NWARP; w++) s += wpart[w];
        wpart[0] = 1.0f / fmaxf(s, 1e-12f);
    }
    __syncthreads();

    // ---- Phase 3b: scatter normalized values ----
    const float inv = wpart[0];
    float* orow = out + (size_t)i * NROWS;
    for (int t = tid; t < m; t += BLOCK)
        orow[nzidx[t]] = evals[t] * inv;
}

extern "C" void kernel_launch(void* const* d_in, const int* in_sizes, int n_in,
                              void* d_out, int out_size)
{
    const float* feats = (const float*)d_in[0];
    const float* adj   = (const float*)d_in[1];
    float* out         = (float*)d_out;
    distance_sparse_kernel<<<NROWS, BLOCK>>>(feats, adj, out);
}

// round 6
// speedup vs baseline: 1.0090x; 1.0090x over previous
#include <cuda_runtime.h>

#define NROWS 2048
#define DFEAT 128
#define BLOCK 256
#define NWARP (BLOCK / 32)

__global__ __launch_bounds__(BLOCK, 6) void distance_sparse_kernel(
    const float* __restrict__ feats,
    const float* __restrict__ adj,
    float* __restrict__ out)
{
    const int i    = blockIdx.x;
    const int tid  = threadIdx.x;
    const int lane = tid & 31;
    const int warp = tid >> 5;

    __shared__ unsigned short nzidx[NROWS];  // 4 KB
    __shared__ float          evals[NROWS];  // 8 KB
    __shared__ float          wpart[NWARP];
    __shared__ int            cnt;

    // ---- issue adj-row DRAM loads first (long pole) ----
    const float4* arow4 = reinterpret_cast<const float4*>(adj + (size_t)i * NROWS);
    const float4 a0 = arow4[tid];
    const float4 a1 = arow4[tid + BLOCK];

    // fi: lane l holds feats[i][4l..4l+3]
    const float4 fi = reinterpret_cast<const float4*>(feats + (size_t)i * DFEAT)[lane];

    // ---- zero-fill output row early: fire-and-forget stores drain during
    //      phases 1-3a; ordered before the scatter by the epilogue barriers ----
    float4* orow4 = reinterpret_cast<float4*>(out + (size_t)i * NROWS);
    const float4 z = make_float4(0.f, 0.f, 0.f, 0.f);
    orow4[tid]         = z;
    orow4[tid + BLOCK] = z;

    if (tid == 0) cnt = 0;
    __syncthreads();

    // ---- Phase 1: ballot-compact nonzero columns ----
    const unsigned lt = (1u << lane) - 1u;
    #pragma unroll
    for (int c = 0; c < 2; c++) {
        const float4 av = (c == 0) ? a0 : a1;
        const int t = tid + c * BLOCK;
        const unsigned b0 = __ballot_sync(0xffffffffu, av.x != 0.0f);
        const unsigned b1 = __ballot_sync(0xffffffffu, av.y != 0.0f);
        const unsigned b2 = __ballot_sync(0xffffffffu, av.z != 0.0f);
        const unsigned b3 = __ballot_sync(0xffffffffu, av.w != 0.0f);
        const int c0 = __popc(b0), c1 = __popc(b1), c2 = __popc(b2), c3 = __popc(b3);
        int base = 0;
        if (lane == 0) base = atomicAdd(&cnt, c0 + c1 + c2 + c3);
        base = __shfl_sync(0xffffffffu, base, 0);
        const int col = t * 4;
        if (av.x != 0.0f) nzidx[base + __popc(b0 & lt)]                = (unsigned short)(col);
        if (av.y != 0.0f) nzidx[base + c0 + __popc(b1 & lt)]           = (unsigned short)(col + 1);
        if (av.z != 0.0f) nzidx[base + c0 + c1 + __popc(b2 & lt)]      = (unsigned short)(col + 2);
        if (av.w != 0.0f) nzidx[base + c0 + c1 + c2 + __popc(b3 & lt)] = (unsigned short)(col + 3);
    }
    __syncthreads();
    const int m = cnt;

    // ---- Phase 2: warp-per-column, 4 columns in flight per warp ----
    for (int c = warp; c * 4 < m; c += NWARP) {
        const int k0 = c * 4;
        const int k1 = k0 + 1, k2 = k0 + 2, k3 = k0 + 3;
        const int j0 = (int)nzidx[k0];
        const int j1 = (int)nzidx[k1 < m ? k1 : k0];
        const int j2 = (int)nzidx[k2 < m ? k2 : k0];
        const int j3 = (int)nzidx[k3 < m ? k3 : k0];
        const float4 f0 = reinterpret_cast<const float4*>(feats + (size_t)j0 * DFEAT)[lane];
        const float4 f1 = reinterpret_cast<const float4*>(feats + (size_t)j1 * DFEAT)[lane];
        const float4 f2 = reinterpret_cast<const float4*>(feats + (size_t)j2 * DFEAT)[lane];
        const float4 f3 = reinterpret_cast<const float4*>(feats + (size_t)j3 * DFEAT)[lane];

        float s0 = (fabsf(fi.x - f0.x) + fabsf(fi.y - f0.y))
                 + (fabsf(fi.z - f0.z) + fabsf(fi.w - f0.w));
        float s1 = (fabsf(fi.x - f1.x) + fabsf(fi.y - f1.y))
                 + (fabsf(fi.z - f1.z) + fabsf(fi.w - f1.w));
        float s2 = (fabsf(fi.x - f2.x) + fabsf(fi.y - f2.y))
                 + (fabsf(fi.z - f2.z) + fabsf(fi.w - f2.w));
        float s3 = (fabsf(fi.x - f3.x) + fabsf(fi.y - f3.y))
                 + (fabsf(fi.z - f3.z) + fabsf(fi.w - f3.w));

        #pragma unroll
        for (int o = 16; o >= 1; o >>= 1) {   // four independent chains, pipelined
            s0 += __shfl_xor_sync(0xffffffffu, s0, o);
            s1 += __shfl_xor_sync(0xffffffffu, s1, o);
            s2 += __shfl_xor_sync(0xffffffffu, s2, o);
            s3 += __shfl_xor_sync(0xffffffffu, s3, o);
        }
        if (lane == 0) {
            evals[k0] = s0;
            if (k1 < m) evals[k1] = s1;
            if (k2 < m) evals[k2] = s2;
            if (k3 < m) evals[k3] = s3;
        }
    }
    __syncthreads();

    // ---- Phase 3a: batched exp + block reduction of rowsum ----
    float local = 0.0f;
    for (int t = tid; t < m; t += BLOCK) {
        const float e = __expf(-0.01f * evals[t]);
        evals[t] = e;
        local += e;
    }
    #pragma unroll
    for (int o = 16; o >= 1; o >>= 1)
        local += __shfl_xor_sync(0xffffffffu, local, o);
    if (lane == 0) wpart[warp] = local;
    __syncthreads();
    if (tid == 0) {
        float s = 0.0f;
        #pragma unroll
        for (int w = 0; w < NWARP; w++) s += wpart[w];
        wpart[0] = 1.0f / fmaxf(s, 1e-12f);
    }
    __syncthreads();

    // ---- Phase 3b: scatter normalized values ----
    const float inv = wpart[0];
    float* orow = out + (size_t)i * NROWS;
    for (int t = tid; t < m; t += BLOCK)
        orow[nzidx[t]] = evals[t] * inv;
}

extern "C" void kernel_launch(void* const* d_in, const int* in_sizes, int n_in,
                              void* d_out, int out_size)
{
    const float* feats = (const float*)d_in[0];
    const float* adj   = (const float*)d_in[1];
    float* out         = (float*)d_out;
    distance_sparse_kernel<<<NROWS, BLOCK>>>(feats, adj, out);
}

// round 7
// speedup vs baseline: 1.0228x; 1.0137x over previous
#include <cuda_runtime.h>

#define NROWS 2048
#define DFEAT 128
#define BLOCK 256
#define NWARP (BLOCK / 32)

__global__ __launch_bounds__(BLOCK) void distance_sparse_kernel(
    const float* __restrict__ feats,
    const float* __restrict__ adj,
    float* __restrict__ out)
{
    const int i    = blockIdx.x;
    const int tid  = threadIdx.x;
    const int lane = tid & 31;
    const int warp = tid >> 5;
    const int sub  = lane & 7;    // sublane within 8-lane group
    const int grp  = lane >> 3;   // group 0..3: one column per group

    __shared__ unsigned short nzidx[NROWS];  // 4 KB
    __shared__ float          evals[NROWS];  // 8 KB
    __shared__ float          wpart[NWARP];
    __shared__ int            cnt;

    // ---- issue adj-row DRAM loads first (long pole) ----
    const float4* arow4 = reinterpret_cast<const float4*>(adj + (size_t)i * NROWS);
    const float4 a0 = arow4[tid];
    const float4 a1 = arow4[tid + BLOCK];

    // fi for this lane's role: float4 slices sub + 8t, t=0..3
    const float4* fi4p = reinterpret_cast<const float4*>(feats + (size_t)i * DFEAT);
    float4 fi[4];
    #pragma unroll
    for (int t = 0; t < 4; t++) fi[t] = fi4p[sub + 8 * t];

    // ---- zero-fill output row early (fire-and-forget; ordered before the
    //      scatter by the epilogue __syncthreads) ----
    float4* orow4 = reinterpret_cast<float4*>(out + (size_t)i * NROWS);
    const float4 z = make_float4(0.f, 0.f, 0.f, 0.f);
    orow4[tid]         = z;
    orow4[tid + BLOCK] = z;

    if (tid == 0) cnt = 0;
    __syncthreads();

    // ---- Phase 1: ballot-compact nonzero columns ----
    const unsigned lt = (1u << lane) - 1u;
    #pragma unroll
    for (int c = 0; c < 2; c++) {
        const float4 av = (c == 0) ? a0 : a1;
        const int t = tid + c * BLOCK;
        const unsigned b0 = __ballot_sync(0xffffffffu, av.x != 0.0f);
        const unsigned b1 = __ballot_sync(0xffffffffu, av.y != 0.0f);
        const unsigned b2 = __ballot_sync(0xffffffffu, av.z != 0.0f);
        const unsigned b3 = __ballot_sync(0xffffffffu, av.w != 0.0f);
        const int c0 = __popc(b0), c1 = __popc(b1), c2 = __popc(b2), c3 = __popc(b3);
        int base = 0;
        if (lane == 0) base = atomicAdd(&cnt, c0 + c1 + c2 + c3);
        base = __shfl_sync(0xffffffffu, base, 0);
        const int col = t * 4;
        if (av.x != 0.0f) nzidx[base + __popc(b0 & lt)]                = (unsigned short)(col);
        if (av.y != 0.0f) nzidx[base + c0 + __popc(b1 & lt)]           = (unsigned short)(col + 1);
        if (av.z != 0.0f) nzidx[base + c0 + c1 + __popc(b2 & lt)]      = (unsigned short)(col + 2);
        if (av.w != 0.0f) nzidx[base + c0 + c1 + c2 + __popc(b3 & lt)] = (unsigned short)(col + 3);
    }
    __syncthreads();
    const int m = cnt;

    // ---- Phase 2: 8-lane group per column, 4 columns per warp pass,
    //      2x unrolled (up to 8 independent column chains), 3 shfls / 4 cols ----
    for (int k4 = warp; k4 * 4 < m; k4 += 2 * NWARP) {
        const int  idxA = k4 * 4 + grp;
        const int  idxB = (k4 + NWARP) * 4 + grp;
        const bool actA = idxA < m;
        const bool actB = idxB < m;
        const int  jA = actA ? (int)nzidx[idxA] : 0;
        const int  jB = actB ? (int)nzidx[idxB] : 0;
        const float4* fjA = reinterpret_cast<const float4*>(feats + (size_t)jA * DFEAT);
        const float4* fjB = reinterpret_cast<const float4*>(feats + (size_t)jB * DFEAT);

        float sA = 0.0f, sB = 0.0f;
        #pragma unroll
        for (int t = 0; t < 4; t++) {
            const float4 fa = fjA[sub + 8 * t];
            sA += (fabsf(fi[t].x - fa.x) + fabsf(fi[t].y - fa.y))
                + (fabsf(fi[t].z - fa.z) + fabsf(fi[t].w - fa.w));
        }
        #pragma unroll
        for (int t = 0; t < 4; t++) {
            const float4 fb = fjB[sub + 8 * t];
            sB += (fabsf(fi[t].x - fb.x) + fabsf(fi[t].y - fb.y))
                + (fabsf(fi[t].z - fb.z) + fabsf(fi[t].w - fb.w));
        }
        #pragma unroll
        for (int o = 4; o >= 1; o >>= 1) {   // reduce within 8-lane groups; pipelined pair
            sA += __shfl_xor_sync(0xffffffffu, sA, o);
            sB += __shfl_xor_sync(0xffffffffu, sB, o);
        }
        if (sub == 0) {
            if (actA) evals[idxA] = sA;
            if (actB) evals[idxB] = sB;
        }
    }
    __syncthreads();

    // ---- Phase 3a: batched exp + block reduction of rowsum ----
    float local = 0.0f;
    for (int t = tid; t < m; t += BLOCK) {
        const float e = __expf(-0.01f * evals[t]);
        evals[t] = e;
        local += e;
    }
    #pragma unroll
    for (int o = 16; o >= 1; o >>= 1)
        local += __shfl_xor_sync(0xffffffffu, local, o);
    if (lane == 0) wpart[warp] = local;
    __syncthreads();
    if (tid == 0) {
        float s = 0.0f;
        #pragma unroll
        for (int w = 0; w < NWARP; w++) s += wpart[w];
        wpart[0] = 1.0f / fmaxf(s, 1e-12f);
    }
    __syncthreads();

    // ---- Phase 3b: scatter normalized values ----
    const float inv = wpart[0];
    float* orow = out + (size_t)i * NROWS;
    for (int t = tid; t < m; t += BLOCK)
        orow[nzidx[t]] = evals[t] * inv;
}

extern "C" void kernel_launch(void* const* d_in, const int* in_sizes, int n_in,
                              void* d_out, int out_size)
{
    const float* feats = (const float*)d_in[0];
    const float* adj   = (const float*)d_in[1];
    float* out         = (float*)d_out;
    distance_sparse_kernel<<<NROWS, BLOCK>>>(feats, adj, out);
}